// round 7
// baseline (speedup 1.0000x reference)
#include <cuda_runtime.h>
#include <cuda_bf16.h>
#include <math.h>
#include <stdint.h>

#define Cn   256
#define Hn   128
#define Wn   128
#define Bn   2
#define HWn  (Hn*Wn)        // 16384
#define NPIX (Bn*HWn)       // 32768
#define NCn  80
#define Kdcn 2304
#define WSZ  (Cn*Kdcn)      // 589824
#define NCHUNK 72           // 2304/32
#define NELEM (Bn*Cn*HWn)   // 8388608
#define PACKQ (NELEM/4)     // 2097152

// ---- smem layout (bytes), per 128-oc CTA ----
// A: 128 oc x 32 k bf16, row pitch 80B -> 10240 per plane
// B: 32 k x 128 px bf16, row pitch 272B -> 8704 per plane
#define A_HI 0
#define A_LO 10240
#define B_HI 20480
#define B_LO 29184
#define STG  37888
#define META (2*STG)                 // 75776
#define SM_TOTAL (META + 9*128*32)   // 112640

__device__ __forceinline__ uint32_t smem_to_u32(const void* p) {
    uint32_t a;
    asm("{ .reg .u64 t; cvta.to.shared.u64 t, %1; cvt.u32.u64 %0, t; }" : "=r"(a) : "l"(p));
    return a;
}
__device__ __forceinline__ void cpasync16(uint32_t dst, const void* src) {
    asm volatile("cp.async.cg.shared.global [%0], [%1], 16;" :: "r"(dst), "l"(src) : "memory");
}
__device__ __forceinline__ void cpcommit() {
    asm volatile("cp.async.commit_group;" ::: "memory");
}
__device__ __forceinline__ void cpwait0() {
    asm volatile("cp.async.wait_group 0;" ::: "memory");
}
__device__ __forceinline__ void ldsm4(uint32_t r[4], uint32_t addr) {
    asm volatile("ldmatrix.sync.aligned.m8n8.x4.shared.b16 {%0,%1,%2,%3}, [%4];"
        : "=r"(r[0]), "=r"(r[1]), "=r"(r[2]), "=r"(r[3]) : "r"(addr));
}
__device__ __forceinline__ void ldsm4t(uint32_t r[4], uint32_t addr) {
    asm volatile("ldmatrix.sync.aligned.m8n8.x4.trans.shared.b16 {%0,%1,%2,%3}, [%4];"
        : "=r"(r[0]), "=r"(r[1]), "=r"(r[2]), "=r"(r[3]) : "r"(addr));
}
__device__ __forceinline__ void mma16816(float d[4], const uint32_t a[4],
                                         uint32_t b0, uint32_t b1) {
    asm volatile(
        "mma.sync.aligned.m16n8k16.row.col.f32.bf16.bf16.f32 "
        "{%0,%1,%2,%3}, {%4,%5,%6,%7}, {%8,%9}, {%0,%1,%2,%3};"
        : "+f"(d[0]), "+f"(d[1]), "+f"(d[2]), "+f"(d[3])
        : "r"(a[0]), "r"(a[1]), "r"(a[2]), "r"(a[3]), "r"(b0), "r"(b1));
}
__device__ __forceinline__ uint32_t prmt(uint32_t a, uint32_t b, uint32_t sel) {
    uint32_t d; asm("prmt.b32 %0,%1,%2,%3;" : "=r"(d) : "r"(a), "r"(b), "r"(sel));
    return d;
}
// packed pair word: low16 = bf16(v), high16 = bf16(v - bf16(v))
__device__ __forceinline__ uint32_t packpair(float v) {
    __nv_bfloat16 h = __float2bfloat16(v);
    float hf = __bfloat162float(h);
    __nv_bfloat16 l = __float2bfloat16(v - hf);
    uint16_t hb = *reinterpret_cast<uint16_t*>(&h);
    uint16_t lb = *reinterpret_cast<uint16_t*>(&l);
    return (uint32_t)hb | ((uint32_t)lb << 16);
}

// ---------------- scratch ----------------
__device__ uint32_t g_pkX [NELEM];
__device__ uint32_t g_pkA [NELEM];
__device__ uint32_t g_pkB [NELEM];
__device__ uint32_t g_ptspk[NELEM];
__device__ float g_cls [NELEM];
__device__ float g_pts [NELEM];
__device__ float g_bufA[NELEM];
__device__ float g_off [Bn*27*HWn];
__device__ float g_dcn [(size_t)Cn*NPIX];
__device__ __align__(16) __nv_bfloat16 g_whi[9*WSZ];
__device__ __align__(16) __nv_bfloat16 g_wlo[9*WSZ];

struct WPtrs { const float* w[9]; };

// ---------------- fused prep: pack x + split all 9 weights (ONE launch) ----------------
__global__ void __launch_bounds__(256)
prep_kernel(const float* __restrict__ x, WPtrs wp,
            uint32_t* __restrict__ pkX,
            __nv_bfloat16* __restrict__ whi, __nv_bfloat16* __restrict__ wlo)
{
    int gid = blockIdx.x * 256 + threadIdx.x;
    if (gid < PACKQ) {
        float4 v = *reinterpret_cast<const float4*>(x + (size_t)gid*4);
        uint4 w = { packpair(v.x), packpair(v.y), packpair(v.z), packpair(v.w) };
        *reinterpret_cast<uint4*>(pkX + (size_t)gid*4) = w;
    } else {
        int i = gid - PACKQ;                 // < 9*WSZ = 5308416
        int l = i / WSZ, r = i - l*WSZ;
        int oc = r / Kdcn, kp = r - oc*Kdcn;
        int tap = kp >> 8, ic = kp & 255;
        float v = wp.w[l][((size_t)oc*256 + ic)*9 + tap];
        __nv_bfloat16 h = __float2bfloat16(v);
        whi[i] = h;
        wlo[i] = __float2bfloat16(v - __bfloat162float(h));
    }
}

// =====================================================================
// Implicit-GEMM: D[128 oc][128 px] per CTA. 256 threads, 2 CTAs/SM.
// mode 0: conv3x3 pad1 (packed-plane input), bias+relu
// mode 1: dcn + mask; mode 2: dcn no mask (fp32 feat, bilinear), relu
// =====================================================================
__global__ void __launch_bounds__(256, 2)
gemm_kernel(int mode,
            const uint32_t* __restrict__ pkfeat,
            const float* __restrict__ feat,
            const __nv_bfloat16* __restrict__ whi, const __nv_bfloat16* __restrict__ wlo,
            const float* __restrict__ bias, const float* __restrict__ off,
            float* __restrict__ outf, uint32_t* __restrict__ outp)
{
    extern __shared__ __align__(128) char smem[];
    const uint32_t sbase = smem_to_u32(smem);
    const int tid  = threadIdx.x;
    const int wid  = tid >> 5, lane = tid & 31;
    const int nblk = blockIdx.x;
    const int b = nblk >> 7, y = nblk & 127;
    const int ocbase = blockIdx.y * 128;

    const int m0 = (wid & 3) * 32;     // 4 m-warps x 32 oc
    const int n0 = (wid >> 2) * 64;    // 2 n-warps x 64 px

    const int aR = (lane & 7) + ((lane >> 3) & 1) * 8;
    const int aC = (lane >> 4) * 8;
    const int bR = lane & 15;
    const int bC = (lane >> 4) * 8;

    // ---- dcn metadata: bilinear weights+indices per (tap, px), once ----
    if (mode != 0) {
        for (int e = tid; e < 9*128; e += 256) {
            int tap = e >> 7, p = e & 127;
            int ky = tap / 3 - 1, kx = tap % 3 - 1;
            int hw = y * Wn + p;
            const float* offb = off + (size_t)b*27*HWn + hw;
            float offy = __ldg(offb + (size_t)(2*tap)*HWn);
            float offx = __ldg(offb + (size_t)(2*tap + 1)*HWn);
            float py = (float)(y + ky) + offy;
            float px = (float)(p + kx) + offx;
            float fy0 = floorf(py), fx0 = floorf(px);
            float ly = py - fy0, lx = px - fx0;
            bool vy0 = (fy0 >= 0.f)       && (fy0 <= 127.f);
            bool vy1 = (fy0 + 1.f >= 0.f) && (fy0 + 1.f <= 127.f);
            bool vx0 = (fx0 >= 0.f)       && (fx0 <= 127.f);
            bool vx1 = (fx0 + 1.f >= 0.f) && (fx0 + 1.f <= 127.f);
            float w00 = (1.f-ly)*(1.f-lx) * ((vy0 && vx0) ? 1.f : 0.f);
            float w01 = (1.f-ly)*lx       * ((vy0 && vx1) ? 1.f : 0.f);
            float w10 = ly*(1.f-lx)       * ((vy1 && vx0) ? 1.f : 0.f);
            float w11 = ly*lx             * ((vy1 && vx1) ? 1.f : 0.f);
            if (mode == 1) {
                float m = __ldg(offb + (size_t)(18 + tap)*HWn);
                w00 *= m; w01 *= m; w10 *= m; w11 *= m;
            }
            int iy0 = min(max((int)fy0,     0), Hn-1);
            int iy1 = min(max((int)fy0 + 1, 0), Hn-1);
            int ix0 = min(max((int)fx0,     0), Wn-1);
            int ix1 = min(max((int)fx0 + 1, 0), Wn-1);
            char* mb = smem + META + e*32;
            *reinterpret_cast<float4*>(mb) = make_float4(w00, w01, w10, w11);
            *reinterpret_cast<int4*>(mb + 16) =
                make_int4(iy0*Wn + ix0, iy0*Wn + ix1, iy1*Wn + ix0, iy1*Wn + ix1);
        }
        __syncthreads();
    }

    float acc[16][4];
    #pragma unroll
    for (int i = 0; i < 16; i++)
        #pragma unroll
        for (int j = 0; j < 4; j++) acc[i][j] = 0.f;

    // ---------------- loader ----------------
    auto load_chunk = [&](int stg, int cc) {
        char* s = smem + stg * STG;
        uint32_t su = sbase + stg * STG;
        // A: 128 oc x 32 k, hi+lo via cp.async (pure copy)
        {
            int row = tid >> 1, seg = tid & 1;
            size_t gi = (size_t)(ocbase + row) * Kdcn + cc * 32 + seg * 16;
            uint32_t so = (uint32_t)(row * 80 + seg * 32);
            cpasync16(su + A_HI + so,      whi + gi);
            cpasync16(su + A_HI + so + 16, whi + gi + 8);
            cpasync16(su + A_LO + so,      wlo + gi);
            cpasync16(su + A_LO + so + 16, wlo + gi + 8);
        }
        cpcommit();

        const int tap = cc >> 3;
        const int ic0 = (cc & 7) * 32;
        const int ky = tap / 3 - 1, kx = tap % 3 - 1;

        if (mode == 0) {
            // B: 32 k x 128 px from packed planes; thread: k = tid>>3, 16 px
            int k   = tid >> 3;
            int px0 = (tid & 7) * 16;
            int yy  = y + ky;
            char* bh = s + B_HI + k*272;
            char* bl = s + B_LO + k*272;
            if (yy < 0 || yy >= Hn) {
                uint2 z = {0u, 0u};
                #pragma unroll
                for (int q = 0; q < 4; q++) {
                    *reinterpret_cast<uint2*>(bh + (px0 + q*4)*2) = z;
                    *reinterpret_cast<uint2*>(bl + (px0 + q*4)*2) = z;
                }
            } else {
                const uint32_t* src = pkfeat + ((size_t)(b*Cn + ic0 + k))*HWn + yy*Wn;
                if (kx == 0) {
                    #pragma unroll
                    for (int q = 0; q < 4; q++) {
                        uint4 w = *reinterpret_cast<const uint4*>(src + px0 + q*4);
                        uint2 hv = { prmt(w.x, w.y, 0x5410), prmt(w.z, w.w, 0x5410) };
                        uint2 lv = { prmt(w.x, w.y, 0x7632), prmt(w.z, w.w, 0x7632) };
                        *reinterpret_cast<uint2*>(bh + (px0 + q*4)*2) = hv;
                        *reinterpret_cast<uint2*>(bl + (px0 + q*4)*2) = lv;
                    }
                } else {
                    #pragma unroll
                    for (int q = 0; q < 4; q++) {
                        uint32_t w[4];
                        #pragma unroll
                        for (int i = 0; i < 4; i++) {
                            int x = px0 + q*4 + i + kx;
                            w[i] = ((unsigned)x < (unsigned)Wn) ? __ldg(src + x) : 0u;
                        }
                        uint2 hv = { prmt(w[0], w[1], 0x5410), prmt(w[2], w[3], 0x5410) };
                        uint2 lv = { prmt(w[0], w[1], 0x7632), prmt(w[2], w[3], 0x7632) };
                        *reinterpret_cast<uint2*>(bh + (px0 + q*4)*2) = hv;
                        *reinterpret_cast<uint2*>(bl + (px0 + q*4)*2) = lv;
                    }
                }
            }
        } else {
            // B via bilinear gather with cached metadata
            int p = tid & 127, g = tid >> 7;   // g in {0,1}, 16 channels each
            const char* mb = smem + META + (tap*128 + p)*32;
            float4 wv = *reinterpret_cast<const float4*>(mb);
            int4  iv = *reinterpret_cast<const int4*>(mb + 16);
            const float* fb = feat + ((size_t)(b*Cn + ic0 + g*16))*HWn;
            #pragma unroll
            for (int j = 0; j < 16; j++) {
                const float* f = fb + (size_t)j*HWn;
                float v = wv.x*__ldg(f + iv.x) + wv.y*__ldg(f + iv.y)
                        + wv.z*__ldg(f + iv.z) + wv.w*__ldg(f + iv.w);
                int k = g*16 + j;
                uint32_t pk = packpair(v);
                *reinterpret_cast<uint16_t*>(s + B_HI + k*272 + p*2) = (uint16_t)(pk & 0xFFFF);
                *reinterpret_cast<uint16_t*>(s + B_LO + k*272 + p*2) = (uint16_t)(pk >> 16);
            }
        }
    };

    // ---------------- compute ----------------
    auto compute = [&](int stg) {
        uint32_t sa_hi = sbase + stg*STG + A_HI + (uint32_t)((m0 + aR)*80 + aC*2);
        uint32_t sa_lo = sa_hi + (A_LO - A_HI);
        uint32_t sb_hi = sbase + stg*STG + B_HI + (uint32_t)(bR*272 + (n0 + bC)*2);
        uint32_t sb_lo = sb_hi + (B_LO - B_HI);
        #pragma unroll
        for (int s2 = 0; s2 < 2; s2++) {
            uint32_t ah[2][4], al[2][4];
            ldsm4(ah[0], sa_hi + s2*32);
            ldsm4(ah[1], sa_hi + s2*32 + 16*80);
            ldsm4(al[0], sa_lo + s2*32);
            ldsm4(al[1], sa_lo + s2*32 + 16*80);
            #pragma unroll
            for (int nb = 0; nb < 4; nb++) {
                uint32_t bh[4], bl[4];
                ldsm4t(bh, sb_hi + s2*16*272 + nb*32);
                ldsm4t(bl, sb_lo + s2*16*272 + nb*32);
                #pragma unroll
                for (int mt = 0; mt < 2; mt++) {
                    mma16816(acc[mt*8 + 2*nb],     ah[mt], bh[0], bh[1]);
                    mma16816(acc[mt*8 + 2*nb + 1], ah[mt], bh[2], bh[3]);
                    mma16816(acc[mt*8 + 2*nb],     ah[mt], bl[0], bl[1]);
                    mma16816(acc[mt*8 + 2*nb + 1], ah[mt], bl[2], bl[3]);
                    mma16816(acc[mt*8 + 2*nb],     al[mt], bh[0], bh[1]);
                    mma16816(acc[mt*8 + 2*nb + 1], al[mt], bh[2], bh[3]);
                }
            }
        }
    };

    // ---------------- pipelined main loop ----------------
    load_chunk(0, 0);
    cpwait0();
    __syncthreads();
    for (int c = 0; c < NCHUNK; c++) {
        int cur = c & 1;
        if (c + 1 < NCHUNK) load_chunk(cur ^ 1, c + 1);
        compute(cur);
        cpwait0();
        __syncthreads();
    }

    // ---------------- epilogue ----------------
    const int r  = lane >> 2;
    const int c2 = (lane & 3) * 2;
    #pragma unroll
    for (int mt = 0; mt < 2; mt++) {
        int ocr = ocbase + m0 + mt*16 + r;
        float b0 = (mode == 0) ? bias[ocr]     : 0.f;
        float b1 = (mode == 0) ? bias[ocr + 8] : 0.f;
        #pragma unroll
        for (int nt = 0; nt < 8; nt++) {
            float* d = acc[mt*8 + nt];
            int x = n0 + nt*8 + c2;
            float v00 = fmaxf(d[0] + b0, 0.f), v01 = fmaxf(d[1] + b0, 0.f);
            float v10 = fmaxf(d[2] + b1, 0.f), v11 = fmaxf(d[3] + b1, 0.f);
            size_t o0, o1;
            if (mode == 0) {
                o0 = ((size_t)(b*Cn + ocr))*HWn     + y*Wn + x;
                o1 = ((size_t)(b*Cn + ocr + 8))*HWn + y*Wn + x;
            } else {
                o0 = (size_t)ocr*NPIX       + (size_t)b*HWn + y*Wn + x;
                o1 = (size_t)(ocr + 8)*NPIX + (size_t)b*HWn + y*Wn + x;
            }
            if (outf) {
                float2 f0 = { v00, v01 }, f1 = { v10, v11 };
                *reinterpret_cast<float2*>(outf + o0) = f0;
                *reinterpret_cast<float2*>(outf + o1) = f1;
            }
            if (outp) {
                uint2 p0 = { packpair(v00), packpair(v01) };
                uint2 p1 = { packpair(v10), packpair(v11) };
                *reinterpret_cast<uint2*>(outp + o0) = p0;
                *reinterpret_cast<uint2*>(outp + o1) = p1;
            }
        }
    }
}

// ---------------- small kernels ----------------
__global__ void __launch_bounds__(256)
conv1x1_27_kernel(const float* __restrict__ in, const float* __restrict__ wgt,
                  const float* __restrict__ bias, float* __restrict__ out)
{
    __shared__ float ws[Cn*27];
    for (int idx = threadIdx.x; idx < Cn*27; idx += 256) {
        int o = idx >> 8, ic = idx & 255;
        ws[ic*27 + o] = wgt[(size_t)o*Cn + ic];
    }
    __syncthreads();
    int p  = blockIdx.x * 256 + threadIdx.x;
    int b  = p >> 14;
    int hw = p & (HWn - 1);
    float acc[27];
    #pragma unroll
    for (int o = 0; o < 27; o++) acc[o] = 0.f;
    const float* ip = in + (size_t)b*Cn*HWn + hw;
    for (int ic = 0; ic < Cn; ic++) {
        float v = __ldg(ip + (size_t)ic*HWn);
        #pragma unroll
        for (int o = 0; o < 27; o++) acc[o] += v * ws[ic*27 + o];
    }
    #pragma unroll
    for (int o = 0; o < 27; o++)
        out[((size_t)(b*27) + o)*HWn + hw] = acc[o] + bias[o];
}

__global__ void __launch_bounds__(256)
conv1x1_cls_kernel(const float* __restrict__ in, const float* __restrict__ wgt,
                   const float* __restrict__ bias, float* __restrict__ out)
{
    __shared__ float ws[Cn*16];
    int g = blockIdx.y;
    for (int idx = threadIdx.x; idx < Cn*16; idx += 256) {
        int j = idx >> 8, ic = idx & 255;
        ws[ic*16 + j] = wgt[(size_t)(g*16 + j)*Cn + ic];
    }
    __syncthreads();
    int p  = blockIdx.x * 256 + threadIdx.x;
    int b  = p >> 14;
    int hw = p & (HWn - 1);
    float acc[16];
    #pragma unroll
    for (int j = 0; j < 16; j++) acc[j] = 0.f;
    for (int ic = 0; ic < Cn; ic++) {
        float v = __ldg(&in[(size_t)ic*NPIX + p]);
        #pragma unroll
        for (int j = 0; j < 16; j++) acc[j] += v * ws[ic*16 + j];
    }
    #pragma unroll
    for (int j = 0; j < 16; j++) {
        int oc = g*16 + j;
        out[((size_t)(b*NCn) + oc)*HWn + hw] = acc[j] + bias[oc];
    }
}

__global__ void __launch_bounds__(256)
ref_fused_kernel(const float* __restrict__ in, const float* __restrict__ wgt,
                 const float* __restrict__ bias, const float* __restrict__ off,
                 float* __restrict__ dout)
{
    __shared__ float ws[Cn*18];
    for (int idx = threadIdx.x; idx < Cn*18; idx += 256) {
        int o = idx >> 8, ic = idx & 255;
        ws[ic*18 + o] = wgt[(size_t)o*Cn + ic];
    }
    __syncthreads();
    int p  = blockIdx.x * 256 + threadIdx.x;
    int b  = p >> 14;
    int hw = p & (HWn - 1);
    float acc[18];
    #pragma unroll
    for (int o = 0; o < 18; o++) acc[o] = 0.f;
    for (int ic = 0; ic < Cn; ic++) {
        float v = __ldg(&in[(size_t)ic*NPIX + p]);
        #pragma unroll
        for (int o = 0; o < 18; o++) acc[o] += v * ws[ic*18 + o];
    }
    float refine[18];
    #pragma unroll
    for (int o = 0; o < 18; o++)
        refine[o] = acc[o] + bias[o] + off[((size_t)(b*27) + o)*HWn + hw];
    float m0 = 0.f, m1 = 0.f;
    #pragma unroll
    for (int q = 0; q < 9; q++) { m0 += refine[2*q]; m1 += refine[2*q + 1]; }
    m0 *= (1.f/9.f); m1 *= (1.f/9.f);
    float wh0 = 0.f, wh1 = 0.f;
    #pragma unroll
    for (int q = 0; q < 9; q++) {
        wh0 = fmaxf(wh0, fabsf(refine[2*q]     + m0));
        wh1 = fmaxf(wh1, fabsf(refine[2*q + 1] + m1));
    }
    const size_t OUT_WH  = (size_t)Bn*NCn*HWn;
    const size_t OUT_REG = OUT_WH + (size_t)Bn*2*HWn;
    dout[OUT_WH  + ((size_t)(b*2) + 0)*HWn + hw] = wh0;
    dout[OUT_WH  + ((size_t)(b*2) + 1)*HWn + hw] = wh1;
    dout[OUT_REG + ((size_t)(b*2) + 0)*HWn + hw] = m0;
    dout[OUT_REG + ((size_t)(b*2) + 1)*HWn + hw] = m1;
}

// =====================================================================
extern "C" void kernel_launch(void* const* d_in, const int* in_sizes, int n_in,
                              void* d_out, int out_size)
{
    const float* x           = (const float*)d_in[0];
    WPtrs wp;
    wp.w[0] = (const float*)d_in[1];   // cls_w0
    wp.w[1] = (const float*)d_in[5];   // cls_w1
    wp.w[2] = (const float*)d_in[9];   // cls_w2
    wp.w[3] = (const float*)d_in[3];   // reg_w0
    wp.w[4] = (const float*)d_in[7];   // reg_w1
    wp.w[5] = (const float*)d_in[11];  // reg_w2
    wp.w[6] = (const float*)d_in[13];  // init_conv_w
    wp.w[7] = (const float*)d_in[17];  // dcn_cls_w
    wp.w[8] = (const float*)d_in[20];  // dcn_ref_w
    const float* cls_b0      = (const float*)d_in[2];
    const float* cls_b1      = (const float*)d_in[6];
    const float* cls_b2      = (const float*)d_in[10];
    const float* reg_b0      = (const float*)d_in[4];
    const float* reg_b1      = (const float*)d_in[8];
    const float* reg_b2      = (const float*)d_in[12];
    const float* init_conv_b = (const float*)d_in[14];
    const float* init_out_w  = (const float*)d_in[15];
    const float* init_out_b  = (const float*)d_in[16];
    const float* cls_out_w   = (const float*)d_in[18];
    const float* cls_out_b   = (const float*)d_in[19];
    const float* ref_out_w   = (const float*)d_in[21];
    const float* ref_out_b   = (const float*)d_in[22];
    float* out = (float*)d_out;

    uint32_t *pkX, *pkA, *pkB, *ptspk;
    float *cls, *pts, *bufA, *off, *dcn;
    __nv_bfloat16 *whi, *wlo;
    cudaGetSymbolAddress((void**)&pkX,  g_pkX);
    cudaGetSymbolAddress((void**)&pkA,  g_pkA);
    cudaGetSymbolAddress((void**)&pkB,  g_pkB);
    cudaGetSymbolAddress((void**)&ptspk,g_ptspk);
    cudaGetSymbolAddress((void**)&cls,  g_cls);
    cudaGetSymbolAddress((void**)&pts,  g_pts);
    cudaGetSymbolAddress((void**)&bufA, g_bufA);
    cudaGetSymbolAddress((void**)&off,  g_off);
    cudaGetSymbolAddress((void**)&dcn,  g_dcn);
    cudaGetSymbolAddress((void**)&whi,  g_whi);
    cudaGetSymbolAddress((void**)&wlo,  g_wlo);

    cudaFuncSetAttribute(gemm_kernel, cudaFuncAttributeMaxDynamicSharedMemorySize, SM_TOTAL);

    #define GEMM(md, pk_, f_, l, bias_, off_, of_, op_) \
        gemm_kernel<<<dim3(256, 2), 256, SM_TOTAL>>>(md, pk_, f_, whi + (size_t)(l)*WSZ, \
                                                     wlo + (size_t)(l)*WSZ, bias_, off_, of_, op_)

    // single prep launch, then all heavy launches are gemm (profiler lands on gemm)
    prep_kernel<<<(PACKQ + 9*WSZ)/256, 256>>>(x, wp, pkX, whi, wlo);

    // cls tower
    GEMM(0, pkX, nullptr, 0, cls_b0, nullptr, nullptr, pkA);
    GEMM(0, pkA, nullptr, 1, cls_b1, nullptr, nullptr, pkB);
    GEMM(0, pkB, nullptr, 2, cls_b2, nullptr, cls, nullptr);
    // reg tower
    GEMM(0, pkX, nullptr, 3, reg_b0, nullptr, nullptr, pkA);
    GEMM(0, pkA, nullptr, 4, reg_b1, nullptr, nullptr, pkB);
    GEMM(0, pkB, nullptr, 5, reg_b2, nullptr, pts, ptspk);
    // init branch
    GEMM(0, ptspk, nullptr, 6, init_conv_b, nullptr, bufA, nullptr);
    conv1x1_27_kernel<<<128, 256>>>(bufA, init_out_w, init_out_b, off);

    // cls dcn (mask) -> cls head
    GEMM(1, nullptr, cls, 7, nullptr, off, dcn, nullptr);
    conv1x1_cls_kernel<<<dim3(128, 5), 256>>>(dcn, cls_out_w, cls_out_b, out);

    // ref dcn (no mask) -> fused refine/wh/reg
    GEMM(2, nullptr, pts, 8, nullptr, off, dcn, nullptr);
    ref_fused_kernel<<<128, 256>>>(dcn, ref_out_w, ref_out_b, off, out);
}